// round 4
// baseline (speedup 1.0000x reference)
#include <cuda_runtime.h>

#define RANK     64
#define WIN      11
#define PADW     5
#define TILE     256
#define THREADS  256
#define XSTRIDE  267   // TILE + 2*PADW + 1 ; 267 mod 32 = 11, coprime with 32 -> conflict-free

// dynamic smem layout (floats):
//   Wsh  [64*64]          = 4096
//   bsh  [64]             = 64
//   xsT  [64][XSTRIDE]    = 17088
//   pS   [WIN][TILE]      = 2816
#define SMEM_FLOATS (4096 + 64 + 64*XSTRIDE + WIN*TILE)
#define SMEM_BYTES  (SMEM_FLOATS * 4)

__global__ __launch_bounds__(THREADS, 2)
void attn_w_kernel(const float* __restrict__ tf,
                   const float* __restrict__ W,
                   const float* __restrict__ b,
                   float* __restrict__ out,
                   int length)
{
    extern __shared__ float sm[];
    float* Wsh = sm;                       // [c][k] row-major, matches W (out,in)
    float* bsh = Wsh + RANK * RANK;
    float* xsT = bsh + RANK;               // transposed tile [k][rowpos]
    float* pS  = xsT + RANK * XSTRIDE;     // [w][tile_row]

    const int tid = threadIdx.x;
    const int row0 = blockIdx.x * TILE;

    // ---- load W, b into shared (coalesced) ----
    #pragma unroll 4
    for (int i = tid; i < RANK * RANK; i += THREADS) Wsh[i] = W[i];
    if (tid < RANK) bsh[tid] = b[tid];

    // ---- load x tile (TILE + 2*PADW rows) transposed into shared ----
    // global read coalesced (row-major); shared store stride XSTRIDE -> 11c mod 32, conflict-free
    for (int e = tid; e < (TILE + 2 * PADW) * RANK; e += THREADS) {
        int rr = e >> 6;
        int c  = e & 63;
        int g  = row0 - PADW + rr;
        float v = (g >= 0 && g < length) ? tf[g * RANK + c] : 0.0f;
        xsT[c * XSTRIDE + rr] = v;
    }
    __syncthreads();

    // ---- per-lane row: tile row j, own data at xsT[*][j+PADW] ----
    const int j = tid;
    const int p = j + PADW;

    // preload own x row into registers (lane-consecutive LDS, conflict-free)
    float x[RANK];
    #pragma unroll
    for (int k = 0; k < RANK; k++) x[k] = xsT[k * XSTRIDE + p];

    float score[WIN];
    #pragma unroll
    for (int w = 0; w < WIN; w++) score[w] = 0.0f;

    // ---- fused GEMV(tanh) + banded score accumulation, c in chunks of 4 ----
    #pragma unroll 1
    for (int c0 = 0; c0 < RANK; c0 += 4) {
        float v[4];
        #pragma unroll
        for (int cc = 0; cc < 4; cc++) {
            const int c = c0 + cc;
            float acc = bsh[c];
            const float4* wr = (const float4*)(Wsh + c * RANK);
            #pragma unroll
            for (int k4 = 0; k4 < RANK / 4; k4++) {
                float4 wv = wr[k4];            // LDS.128 broadcast
                acc = fmaf(x[4 * k4 + 0], wv.x, acc);
                acc = fmaf(x[4 * k4 + 1], wv.y, acc);
                acc = fmaf(x[4 * k4 + 2], wv.z, acc);
                acc = fmaf(x[4 * k4 + 3], wv.w, acc);
            }
            // fast tanh: (e^{2a}-1)/(e^{2a}+1)
            float e = __expf(2.0f * acc);
            v[cc] = 1.0f - __fdividef(2.0f, e + 1.0f);
        }
        #pragma unroll
        for (int cc = 0; cc < 4; cc++) {
            const float* xc = xsT + (c0 + cc) * XSTRIDE + j;   // window rows j..j+10
            #pragma unroll
            for (int w = 0; w < WIN; w++)
                score[w] = fmaf(xc[w], v[cc], score[w]);
        }
    }

    // ---- scale + softmax over window (fully per-lane) ----
    float mx = -1e30f;
    #pragma unroll
    for (int w = 0; w < WIN; w++) { score[w] *= 0.125f; mx = fmaxf(mx, score[w]); }
    float ssum = 0.0f;
    #pragma unroll
    for (int w = 0; w < WIN; w++) { score[w] = __expf(score[w] - mx); ssum += score[w]; }
    float inv = __fdividef(1.0f, ssum);
    #pragma unroll
    for (int w = 0; w < WIN; w++) pS[w * TILE + j] = score[w] * inv;
    __syncthreads();

    // ---- output pass, c-major remap for coalesced STG ----
    // thread t -> col c = t&63, rows jj = t>>6 + 4*iter
    const int c  = tid & 63;
    const int j0 = tid >> 6;
    #pragma unroll 1
    for (int jj = j0; jj < TILE; jj += 4) {
        int gr = row0 + jj;
        if (gr < length) {
            const float* xc = xsT + c * XSTRIDE + jj;   // stride-267 across lanes, conflict-free
            float o = 0.0f;
            #pragma unroll
            for (int w = 0; w < WIN; w++)
                o = fmaf(pS[w * TILE + jj], xc[w], o);  // pS broadcast per warp
            out[gr * RANK + c] = o;                     // coalesced
        }
    }
}

extern "C" void kernel_launch(void* const* d_in, const int* in_sizes, int n_in,
                              void* d_out, int out_size)
{
    const float* tf = (const float*)d_in[0];
    const float* W  = (const float*)d_in[1];
    const float* b  = (const float*)d_in[2];
    float* out      = (float*)d_out;

    const int length = in_sizes[0] / RANK;
    const int grid   = (length + TILE - 1) / TILE;

    cudaFuncSetAttribute(attn_w_kernel,
                         cudaFuncAttributeMaxDynamicSharedMemorySize, SMEM_BYTES);
    attn_w_kernel<<<grid, THREADS, SMEM_BYTES>>>(tf, W, b, out, length);
}